// round 14
// baseline (speedup 1.0000x reference)
#include <cuda_runtime.h>
#include <math.h>
#include <stdint.h>

#define HW    64
#define NPIX  4096
#define NEDGE 8064      // 4032 horizontal + 4032 vertical
#define NTHR  1024
#define REPS  (NPIX / NTHR)   // 4
#define FULLM 0xFFFFFFFFu
#define SENT  0x7FFFFFFF

__device__ float g_bb[4][NPIX];
__device__ float g_bd[4][NPIX];
__device__ int   g_k1[4];
__device__ int   g_k2[4];
__device__ int   g_done;        // zero-init; finisher resets to 0 for graph replay

__device__ __forceinline__ unsigned ford(float f) {
    unsigned u = __float_as_uint(f);
    return (u & 0x80000000u) ? ~u : (u | 0x80000000u);
}
__device__ __forceinline__ float iford(unsigned m) {
    unsigned u = (m & 0x80000000u) ? (m ^ 0x80000000u) : ~m;
    return __uint_as_float(u);
}

// Shared layout:
//   val  f32[4096]   @0        16384
//   par  i32[4096]   @16384    16384
//   best u64[4096]   @32768    32768   (per-root best edge; then loss scratch)
//   mkey u64[4096]   @65536    32768   (plist u16[] during merge rounds; persistence keys after)
//   barB f32[4096]   @98304    16384
//   barD f32[4096]   @114688   16384
//   ctrl i32[16]     @132096      64
//   hk   u64[4096]   @132160   32768
//   peak i32[4096]   @164928   16384
//   eA   u16[8064]   @181312   16128   (cross-edge lists, ping-pong)
//   eB   u16[8064]   @197440   16128  -> 213568
#define SMEM_BYTES 213568

extern __shared__ unsigned char smem_raw[];

__device__ __forceinline__ void edge_decode(int e, int& u, int& v) {
    if (e < 4032) { int r = e / 63, c = e - r * 63; u = r * 64 + c; v = u + 1; }
    else          { u = e - 4032; v = u + 64; }
}

__device__ __forceinline__ void block_bitonic(unsigned long long* key, int P, int tid) {
    for (int k = 2; k <= P; k <<= 1) {
        for (int j = k >> 1; j > 0; j >>= 1) {
            for (int i = tid; i < P; i += NTHR) {
                int l = i ^ j;
                if (l > i) {
                    bool up = ((i & k) == 0);
                    unsigned long long a = key[i], b = key[l];
                    if ((a > b) == up) { key[i] = b; key[l] = a; }
                }
            }
            __syncthreads();
        }
    }
}

// hybrid bitonic for P == 1024 with 1024 threads (21 block barriers)
__device__ __forceinline__ void hybrid_bitonic_1024(unsigned long long* key, int tid) {
    const int lane = tid & 31;
    unsigned long long x = key[tid];
    #pragma unroll
    for (int k = 2; k <= 32; k <<= 1) {
        const bool dirUp = ((tid & k) == 0);
        #pragma unroll
        for (int j = k >> 1; j > 0; j >>= 1) {
            unsigned long long p = __shfl_xor_sync(FULLM, x, j);
            bool lower = ((lane & j) == 0);
            bool takeMin = (lower == dirUp);
            unsigned long long mn = (x < p) ? x : p;
            unsigned long long mx = (x < p) ? p : x;
            x = takeMin ? mn : mx;
        }
    }
    key[tid] = x;
    __syncthreads();
    #pragma unroll
    for (int k = 64; k <= 1024; k <<= 1) {
        const bool dirUp = ((tid & k) == 0);
        for (int j = k >> 1; j >= 32; j >>= 1) {
            int l = tid ^ j;
            if (l > tid) {
                unsigned long long a = key[tid], b = key[l];
                if ((a > b) == dirUp) { key[tid] = b; key[l] = a; }
            }
            __syncthreads();
        }
        x = key[tid];
        #pragma unroll
        for (int j = 16; j > 0; j >>= 1) {
            unsigned long long p = __shfl_xor_sync(FULLM, x, j);
            bool lower = ((lane & j) == 0);
            bool takeMin = (lower == dirUp);
            unsigned long long mn = (x < p) ? x : p;
            unsigned long long mx = (x < p) ? p : x;
            x = takeMin ? mn : mx;
        }
        key[tid] = x;
        __syncthreads();
    }
}

__device__ __forceinline__ void sort_keys(unsigned long long* key, int n, int tid) {
    if (n <= 1024) hybrid_bitonic_1024(key, tid);
    else           block_bitonic(key, (n <= 2048) ? 2048 : 4096, tid);
}

__global__ void __launch_bounds__(NTHR)
diagram_kernel(const float* __restrict__ input, const float* __restrict__ target,
               float* __restrict__ out)
{
    const int s    = blockIdx.x & 3;
    const int kind = blockIdx.x >> 2;
    const int tid  = threadIdx.x;

    float* val = (float*)smem_raw;
    int*   par = (int*)(smem_raw + 16384);
    unsigned long long* best = (unsigned long long*)(smem_raw + 32768);
    unsigned long long* mkey = (unsigned long long*)(smem_raw + 65536);
    unsigned short* plist = (unsigned short*)(smem_raw + 65536);   // dead once mkey is needed
    float* barB = (float*)(smem_raw + 98304);
    float* barD = (float*)(smem_raw + 114688);
    int* ctrl = (int*)(smem_raw + 132096);
    unsigned* uctrl = (unsigned*)ctrl;
    unsigned long long* hk = (unsigned long long*)(smem_raw + 132160);
    int* peak = (int*)(smem_raw + 164928);
    unsigned short* eA = (unsigned short*)(smem_raw + 181312);
    unsigned short* eB = (unsigned short*)(smem_raw + 197440);

    if (tid == 0) {
        ctrl[3] = 0; uctrl[2] = FULLM; uctrl[6] = 0u;
        ctrl[7] = 0; ctrl[8] = 0; ctrl[9] = 0;
    }
    __syncthreads();

    // ---- fill ----
    #pragma unroll
    for (int rep = 0; rep < REPS; ++rep) {
        int i = tid + rep * NTHR;
        float v;
        if (kind == 0) {
            float l0 = input[(s * 2 + 0) * NPIX + i];
            float l1 = input[(s * 2 + 1) * NPIX + i];
            v = 1.0f / (1.0f + expf(l0 - l1));   // == softmax fg channel
        } else {
            v = target[s * NPIX + i];
        }
        val[i] = v;
        if (kind == 0)
            hk[i] = (((unsigned long long)ford(v)) << 12) | (unsigned)(4095 - i);
        unsigned fb = ford(v);
        unsigned wmin = __reduce_min_sync(FULLM, fb);
        unsigned wmax = __reduce_max_sync(FULLM, fb);
        if ((tid & 31) == 0) { atomicMin(&uctrl[2], wmin); atomicMax(&uctrl[6], wmax); }
    }
    __syncthreads();
    const float minv = iford(uctrl[2]);
    const float maxv = iford(uctrl[6]);

    if (kind == 1) {
        // ======== binary target fast path: #components of {val > min} ========
        #pragma unroll
        for (int rep = 0; rep < REPS; ++rep) {
            int i = tid + rep * NTHR;
            par[i] = (val[i] > minv) ? i : SENT;
        }
        __syncthreads();
        for (int round = 0; round < 24; ++round) {
            int hooked = 0;
            #pragma unroll
            for (int rep = 0; rep < REPS; ++rep) {
                int i = tid + rep * NTHR;
                int ri = par[i];
                if (ri != SENT) {
                    int r = i >> 6, c = i & 63;
                    int m = ri;
                    if (r > 0)  { int q = par[i - 64]; if (q < m) m = q; }
                    if (r < 63) { int q = par[i + 64]; if (q < m) m = q; }
                    if (c > 0)  { int q = par[i - 1];  if (q < m) m = q; }
                    if (c < 63) { int q = par[i + 1];  if (q < m) m = q; }
                    if (m < ri) { atomicMin(&par[ri], m); hooked = 1; }
                }
            }
            if (!__syncthreads_or(hooked)) break;
            for (int it = 0; it < 13; ++it) {
                int chg = 0;
                #pragma unroll
                for (int rep = 0; rep < REPS; ++rep) {
                    int i = tid + rep * NTHR;
                    int p = par[i];
                    if (p != SENT) {
                        int pp = par[p];
                        if (p != pp) { par[i] = pp; chg = 1; }
                    }
                }
                if (!__syncthreads_or(chg)) break;
            }
        }
        int cnt = 0;
        #pragma unroll
        for (int rep = 0; rep < REPS; ++rep) {
            int i = tid + rep * NTHR;
            if (par[i] == i) cnt++;
        }
        cnt = __reduce_add_sync(FULLM, cnt);
        if ((tid & 31) == 0) atomicAdd(&ctrl[3], cnt);
        __syncthreads();
        if (tid == 0) g_k2[s] = ctrl[3];
    } else {
        // ======== pred path ========
        // steepest strictly-higher neighbor hook -> peak labels
        #pragma unroll
        for (int rep = 0; rep < REPS; ++rep) {
            int i = tid + rep * NTHR;
            unsigned long long h = hk[i];
            int r = i >> 6, c = i & 63;
            int p = i;
            if      (r < 63 && hk[i + 64] > h) p = i + 64;
            else if (r > 0  && hk[i - 64] > h) p = i - 64;
            else if (c < 63 && hk[i + 1]  > h) p = i + 1;
            else if (c > 0  && hk[i - 1]  > h) p = i - 1;
            par[i] = p;
        }
        __syncthreads();
        for (int it = 0; it < 12; ++it) {
            int chg = 0;
            #pragma unroll
            for (int rep = 0; rep < REPS; ++rep) {
                int i = tid + rep * NTHR;
                int p = par[i]; int pp = par[p];
                if (p != pp) { par[i] = pp; chg = 1; }
            }
            if (!__syncthreads_or(chg)) break;
        }
        #pragma unroll
        for (int rep = 0; rep < REPS; ++rep) {
            int i = tid + rep * NTHR;
            int p = par[i];
            peak[i] = p;
            if (p == i) { int slot = atomicAdd(&ctrl[7], 1); plist[slot] = (unsigned short)i; }
        }
        __syncthreads();
        const int npk = ctrl[7];

        // ---- mutual-best parallel Kruskal (exact) over cross-region edges ----
        // Invariant at each round start: par is flat on peaks (roots = component max-peaks).
        // Mutual-best edges see exactly their sequential component state -> commits exact.
        int Ecur = NEDGE;
        for (int round = 0; Ecur > 0 && round < 4096; ++round) {
            if (tid == 0) ctrl[8 + ((round + 1) & 1)] = 0;
            for (int t = tid; t < npk; t += NTHR) best[plist[t]] = 0ull;
            __syncthreads();                                         // B1

            const unsigned short* src = (round & 1) ? eB : eA;
            unsigned short*       dst = (round & 1) ? eA : eB;
            int* nxt = &ctrl[8 + ((round + 1) & 1)];
            for (int base = 0; base < Ecur; base += NTHR) {
                int idx = base + tid;
                int e = 0; bool keep = false;
                unsigned long long sc = 0; int ru = 0, rv = 0;
                if (idx < Ecur) {
                    e = (round == 0) ? idx : (int)src[idx];
                    int u, v; edge_decode(e, u, v);
                    ru = par[peak[u]]; rv = par[peak[v]];
                    if (ru != rv) {
                        keep = true;
                        unsigned long long hu = hk[u], hv = hk[v];
                        unsigned long long low = hu < hv ? hu : hv;
                        sc = (low << 13) | (unsigned)e;
                    }
                }
                unsigned m = __ballot_sync(FULLM, keep);
                int slot0 = 0;
                if ((tid & 31) == 0 && m) slot0 = atomicAdd(nxt, __popc(m));
                slot0 = __shfl_sync(FULLM, slot0, 0);
                if (keep) {
                    int rank = __popc(m & ((1u << (tid & 31)) - 1));
                    dst[slot0 + rank] = (unsigned short)e;
                    atomicMax(&best[ru], sc);
                    atomicMax(&best[rv], sc);
                }
            }
            __syncthreads();                                         // B2

            // commit pass: mutual-best edges merge; only the young root commits.
            // Races are benign: only par[young-roots] are written, and every
            // read-order produces the identical commit decision.
            for (int t = tid; t < npk; t += NTHR) {
                int r = plist[t];
                if (par[r] != r) continue;
                unsigned long long sc = best[r];
                if (!sc) continue;
                int e = (int)(sc & 0x1FFF);
                int u, v; edge_decode(e, u, v);
                int ru = par[peak[u]], rv = par[peak[v]];
                if (ru == rv) continue;
                if (best[ru] != sc || best[rv] != sc) continue;      // not mutual
                int young, elder;
                if (hk[ru] > hk[rv]) { elder = ru; young = rv; }
                else                 { elder = rv; young = ru; }
                if (r != young) continue;
                par[young] = elder;
                int dIdx = 4095 - (int)((sc >> 13) & 0xFFF);         // death = low endpoint
                float bv = val[young], dv = val[dIdx];
                if (bv > dv) {
                    int slot = atomicAdd(&ctrl[3], 1);
                    barB[slot] = bv; barD[slot] = dv;
                }
            }
            __syncthreads();                                         // B3

            // one jump pass restores flatness (chains have depth <= 2)
            for (int t = tid; t < npk; t += NTHR) {
                int p = plist[t];
                int a = par[p];
                par[p] = par[a];
            }
            __syncthreads();                                         // B4
            Ecur = ctrl[8 + ((round + 1) & 1)];
        }

        // essential bar: single surviving root = global max pixel
        if (tid == 0 && maxv > minv) {
            int slot = atomicAdd(&ctrl[3], 1);
            barB[slot] = maxv; barD[slot] = minv;
        }
        __syncthreads();
        const int nb = ctrl[3];

        // ---- sort bars by persistence descending (plist dead; mkey reuses its space) ----
        const int P2 = (nb <= 1024) ? 1024 : ((nb <= 2048) ? 2048 : 4096);
        for (int i = tid; i < P2; i += NTHR) {
            if (i < nb) {
                float p = barB[i] - barD[i];
                mkey[i] = (((unsigned long long)(~ford(p))) << 32) | (unsigned)i;
            } else {
                mkey[i] = ~0ull;
            }
        }
        __syncthreads();
        sort_keys(mkey, nb, tid);

        for (int i = tid; i < nb; i += NTHR) {
            int idx = (int)(mkey[i] & 0xFFFFFFFFu);
            g_bb[s][i] = barB[idx];
            g_bd[s][i] = barD[idx];
        }
        if (tid == 0) g_k1[s] = nb;
    }

    // ---- fused loss: last block computes the final scalar ----
    __threadfence();
    __syncthreads();
    if (tid == 0) {
        int old = atomicAdd(&g_done, 1);
        ctrl[5] = (old == 7) ? 1 : 0;
    }
    __syncthreads();
    if (!ctrl[5]) return;
    __threadfence();

    float* red = (float*)best;
    float acc = 0.f;
    for (int ss = 0; ss < 4; ++ss) {
        const int K1 = g_k1[ss], K2 = g_k2[ss];
        const int m  = min(K1, K2);
        for (int t = tid; t < K1; t += NTHR) {
            float b = g_bb[ss][t], d = g_bd[ss][t];
            if (t < m) {
                float db = b - 1.0f;
                acc += db * db + d * d;
            } else {
                float q = b - d;
                acc += 0.5f * q * q;
            }
        }
        if (tid == 0 && K2 > K1)
            acc += 0.5f * (float)(K2 - K1);
    }
    #pragma unroll
    for (int off = 16; off > 0; off >>= 1)
        acc += __shfl_xor_sync(FULLM, acc, off);
    if ((tid & 31) == 0) red[tid >> 5] = acc;
    __syncthreads();
    if (tid < 32) {
        float a = red[tid];
        #pragma unroll
        for (int off = 16; off > 0; off >>= 1)
            a += __shfl_xor_sync(FULLM, a, off);
        if (tid == 0) {
            out[0] = a * 0.25f;
            g_done = 0;
        }
    }
}

extern "C" void kernel_launch(void* const* d_in, const int* in_sizes, int n_in,
                              void* d_out, int out_size)
{
    (void)in_sizes; (void)n_in; (void)out_size;
    const float* input  = (const float*)d_in[0];   // (4,2,64,64) float32
    const float* target = (const float*)d_in[1];   // (4,64,64)   float32

    cudaFuncSetAttribute(diagram_kernel,
                         cudaFuncAttributeMaxDynamicSharedMemorySize, SMEM_BYTES);
    diagram_kernel<<<8, NTHR, SMEM_BYTES>>>(input, target, (float*)d_out);
}

// round 15
// speedup vs baseline: 5.1072x; 5.1072x over previous
#include <cuda_runtime.h>
#include <math.h>
#include <stdint.h>

#define HW    64
#define NPIX  4096
#define NEDGE 8064      // 4032 horizontal + 4032 vertical
#define NTHR  1024
#define REPS  (NPIX / NTHR)   // 4
#define FULLM 0xFFFFFFFFu
#define SENT  0x7FFFFFFF

__device__ float g_bb[4][NPIX];
__device__ float g_bd[4][NPIX];
__device__ int   g_k1[4];
__device__ int   g_k2[4];
__device__ int   g_done;        // zero-init; finisher resets to 0 for graph replay

__device__ __forceinline__ unsigned ford(float f) {
    unsigned u = __float_as_uint(f);
    return (u & 0x80000000u) ? ~u : (u | 0x80000000u);
}
__device__ __forceinline__ float iford(unsigned m) {
    unsigned u = (m & 0x80000000u) ? (m ^ 0x80000000u) : ~m;
    return __uint_as_float(u);
}

// Shared layout: (same as R13)
//   val  f32[4096]   @0        16384
//   par  i32[4096]   @16384    16384
//   best u64[4096]   @32768    32768   (Boruvka best; then firstE int[]; then loss scratch)
//   mkey u64[4096]   @65536    32768
//   barB f32[4096]   @98304    16384   (alias: int tmp[4096])
//   barD f32[4096]   @114688   16384   (alias: u16 plist[4096])
//   used u32[252]    @131072    1008   (pairing done-bitmap)
//   ctrl i32[16]     @132096      64
//   hk   u64[4096]   @132160   32768
//   peak i32[4096]   @164928   16384
//   eA   u16[8064]   @181312   16128   (edge lists; then pairing root cache / chain list)
//   eB   u16[8064]   @197440   16128  -> 213568
#define SMEM_BYTES 213568

extern __shared__ unsigned char smem_raw[];

__device__ __forceinline__ void edge_decode(int e, int& u, int& v) {
    if (e < 4032) { int r = e / 63, c = e - r * 63; u = r * 64 + c; v = u + 1; }
    else          { u = e - 4032; v = u + 64; }
}

__device__ __forceinline__ void block_bitonic(unsigned long long* key, int P, int tid) {
    for (int k = 2; k <= P; k <<= 1) {
        for (int j = k >> 1; j > 0; j >>= 1) {
            for (int i = tid; i < P; i += NTHR) {
                int l = i ^ j;
                if (l > i) {
                    bool up = ((i & k) == 0);
                    unsigned long long a = key[i], b = key[l];
                    if ((a > b) == up) { key[i] = b; key[l] = a; }
                }
            }
            __syncthreads();
        }
    }
}

// hybrid bitonic for P == 1024 with 1024 threads (21 block barriers)
__device__ __forceinline__ void hybrid_bitonic_1024(unsigned long long* key, int tid) {
    const int lane = tid & 31;
    unsigned long long x = key[tid];
    #pragma unroll
    for (int k = 2; k <= 32; k <<= 1) {
        const bool dirUp = ((tid & k) == 0);
        #pragma unroll
        for (int j = k >> 1; j > 0; j >>= 1) {
            unsigned long long p = __shfl_xor_sync(FULLM, x, j);
            bool lower = ((lane & j) == 0);
            bool takeMin = (lower == dirUp);
            unsigned long long mn = (x < p) ? x : p;
            unsigned long long mx = (x < p) ? p : x;
            x = takeMin ? mn : mx;
        }
    }
    key[tid] = x;
    __syncthreads();
    #pragma unroll
    for (int k = 64; k <= 1024; k <<= 1) {
        const bool dirUp = ((tid & k) == 0);
        for (int j = k >> 1; j >= 32; j >>= 1) {
            int l = tid ^ j;
            if (l > tid) {
                unsigned long long a = key[tid], b = key[l];
                if ((a > b) == dirUp) { key[tid] = b; key[l] = a; }
            }
            __syncthreads();
        }
        x = key[tid];
        #pragma unroll
        for (int j = 16; j > 0; j >>= 1) {
            unsigned long long p = __shfl_xor_sync(FULLM, x, j);
            bool lower = ((lane & j) == 0);
            bool takeMin = (lower == dirUp);
            unsigned long long mn = (x < p) ? x : p;
            unsigned long long mx = (x < p) ? p : x;
            x = takeMin ? mn : mx;
        }
        key[tid] = x;
        __syncthreads();
    }
}

__device__ __forceinline__ void sort_keys(unsigned long long* key, int n, int tid) {
    if (n <= 1024) hybrid_bitonic_1024(key, tid);
    else           block_bitonic(key, (n <= 2048) ? 2048 : 4096, tid);
}

// one 32-edge speculative Kruskal chunk (proven R7 scheme)
__device__ __forceinline__ void kruskal_chunk(
    bool has, unsigned long long sc,
    int* par, const int* peak, const unsigned long long* hk,
    const float* val, float* barB, float* barD, int* nbars, int lane)
{
    int dIdx = 0, ru = 0, rv = 0;
    unsigned long long hu = 0, hv = 0;
    if (has) {
        int e = (int)(sc & 0x1FFF);
        int uu, vv; edge_decode(e, uu, vv);
        dIdx = 4095 - (int)((sc >> 13) & 0xFFF);
        ru = peak[uu];
        for (;;) { int p = par[ru]; if (p == ru) break; int gp = par[p]; par[ru] = gp; ru = gp; }
        rv = peak[vv];
        for (;;) { int p = par[rv]; if (p == rv) break; int gp = par[p]; par[rv] = gp; rv = gp; }
        hu = hk[ru]; hv = hk[rv];
    }
    __syncwarp(FULLM);
    int young = -1, elder = -1;
    #pragma unroll 4
    for (int k = 0; k < 32; ++k) {
        unsigned pk = 0xFFFFFFFFu;
        if (lane == k && has && ru != rv) {
            if (hu > hv) { elder = ru; young = rv; }
            else         { elder = rv; young = ru; }
            pk = ((unsigned)young << 16) | (unsigned)elder;
        }
        pk = __shfl_sync(FULLM, pk, k);
        if (pk != 0xFFFFFFFFu && lane > k) {
            int yk = (int)(pk >> 16), ek = (int)(pk & 0xFFFFu);
            if (ru == yk) { ru = ek; hu = hk[ek]; }
            if (rv == yk) { rv = ek; hv = hk[ek]; }
        }
    }
    if (young >= 0) {
        par[young] = elder;
        float bv = val[young];
        float dv = val[dIdx];
        if (bv > dv) {
            int slot = atomicAdd(nbars, 1);
            barB[slot] = bv; barD[slot] = dv;
        }
    }
    __syncwarp(FULLM);
}

__global__ void __launch_bounds__(NTHR)
diagram_kernel(const float* __restrict__ input, const float* __restrict__ target,
               float* __restrict__ out)
{
    const int s    = blockIdx.x & 3;
    const int kind = blockIdx.x >> 2;
    const int tid  = threadIdx.x;

    float* val = (float*)smem_raw;
    int*   par = (int*)(smem_raw + 16384);
    unsigned long long* best = (unsigned long long*)(smem_raw + 32768);
    int*   firstE = (int*)(smem_raw + 32768);
    unsigned long long* mkey = (unsigned long long*)(smem_raw + 65536);
    float* barB = (float*)(smem_raw + 98304);
    int*   tmp  = (int*)  (smem_raw + 98304);
    float* barD = (float*)(smem_raw + 114688);
    unsigned short* plist = (unsigned short*)(smem_raw + 114688);
    unsigned* used = (unsigned*)(smem_raw + 131072);
    int* ctrl = (int*)(smem_raw + 132096);
    unsigned* uctrl = (unsigned*)ctrl;
    unsigned long long* hk = (unsigned long long*)(smem_raw + 132160);
    int* peak = (int*)(smem_raw + 164928);
    unsigned short* eA = (unsigned short*)(smem_raw + 181312);
    unsigned short* eB = (unsigned short*)(smem_raw + 197440);

    if (tid == 0) {
        ctrl[0] = 0; ctrl[3] = 0; uctrl[2] = FULLM; uctrl[6] = 0u;
        ctrl[7] = 0; ctrl[8] = 0; ctrl[9] = 0; ctrl[11] = 0;
    }
    __syncthreads();

    // ---- fill ----
    #pragma unroll
    for (int rep = 0; rep < REPS; ++rep) {
        int i = tid + rep * NTHR;
        float v;
        if (kind == 0) {
            float l0 = input[(s * 2 + 0) * NPIX + i];
            float l1 = input[(s * 2 + 1) * NPIX + i];
            v = 1.0f / (1.0f + expf(l0 - l1));   // == softmax fg channel
        } else {
            v = target[s * NPIX + i];
        }
        val[i] = v;
        if (kind == 0)
            hk[i] = (((unsigned long long)ford(v)) << 12) | (unsigned)(4095 - i);
        unsigned fb = ford(v);
        unsigned wmin = __reduce_min_sync(FULLM, fb);
        unsigned wmax = __reduce_max_sync(FULLM, fb);
        if ((tid & 31) == 0) { atomicMin(&uctrl[2], wmin); atomicMax(&uctrl[6], wmax); }
    }
    __syncthreads();
    const float minv = iford(uctrl[2]);
    const float maxv = iford(uctrl[6]);

    if (kind == 1) {
        // ======== binary target fast path: #components of {val > min} ========
        #pragma unroll
        for (int rep = 0; rep < REPS; ++rep) {
            int i = tid + rep * NTHR;
            par[i] = (val[i] > minv) ? i : SENT;
        }
        __syncthreads();
        for (int round = 0; round < 24; ++round) {
            int hooked = 0;
            #pragma unroll
            for (int rep = 0; rep < REPS; ++rep) {
                int i = tid + rep * NTHR;
                int ri = par[i];
                if (ri != SENT) {
                    int r = i >> 6, c = i & 63;
                    int m = ri;
                    if (r > 0)  { int q = par[i - 64]; if (q < m) m = q; }
                    if (r < 63) { int q = par[i + 64]; if (q < m) m = q; }
                    if (c > 0)  { int q = par[i - 1];  if (q < m) m = q; }
                    if (c < 63) { int q = par[i + 1];  if (q < m) m = q; }
                    if (m < ri) { atomicMin(&par[ri], m); hooked = 1; }
                }
            }
            if (!__syncthreads_or(hooked)) break;
            for (int it = 0; it < 13; ++it) {
                int chg = 0;
                #pragma unroll
                for (int rep = 0; rep < REPS; ++rep) {
                    int i = tid + rep * NTHR;
                    int p = par[i];
                    if (p != SENT) {
                        int pp = par[p];
                        if (p != pp) { par[i] = pp; chg = 1; }
                    }
                }
                if (!__syncthreads_or(chg)) break;
            }
        }
        int cnt = 0;
        #pragma unroll
        for (int rep = 0; rep < REPS; ++rep) {
            int i = tid + rep * NTHR;
            if (par[i] == i) cnt++;
        }
        cnt = __reduce_add_sync(FULLM, cnt);
        if ((tid & 31) == 0) atomicAdd(&ctrl[3], cnt);
        __syncthreads();
        if (tid == 0) g_k2[s] = ctrl[3];
    } else {
        // ======== pred path ========
        // steepest strictly-higher neighbor hook -> peak labels
        #pragma unroll
        for (int rep = 0; rep < REPS; ++rep) {
            int i = tid + rep * NTHR;
            unsigned long long h = hk[i];
            int r = i >> 6, c = i & 63;
            int p = i;
            if      (r < 63 && hk[i + 64] > h) p = i + 64;
            else if (r > 0  && hk[i - 64] > h) p = i - 64;
            else if (c < 63 && hk[i + 1]  > h) p = i + 1;
            else if (c > 0  && hk[i - 1]  > h) p = i - 1;
            par[i] = p;
        }
        __syncthreads();
        for (int it = 0; it < 12; ++it) {
            int chg = 0;
            #pragma unroll
            for (int rep = 0; rep < REPS; ++rep) {
                int i = tid + rep * NTHR;
                int p = par[i]; int pp = par[p];
                if (p != pp) { par[i] = pp; chg = 1; }
            }
            if (!__syncthreads_or(chg)) break;
        }
        #pragma unroll
        for (int rep = 0; rep < REPS; ++rep) {
            int i = tid + rep * NTHR;
            int p = par[i];
            peak[i] = p;
            if (p == i) { int slot = atomicAdd(&ctrl[7], 1); plist[slot] = (unsigned short)i; }
        }
        __syncthreads();
        const int npk = ctrl[7];

        // ---- Boruvka over regions with compacted edge lists ----
        int Ecur = NEDGE;
        for (int round = 0; Ecur > 0 && round < 20; ++round) {
            if (tid == 0) ctrl[8 + ((round + 1) & 1)] = 0;
            for (int t = tid; t < npk; t += NTHR) best[plist[t]] = 0ull;
            __syncthreads();                                         // B1

            const unsigned short* src = (round & 1) ? eB : eA;
            unsigned short*       dst = (round & 1) ? eA : eB;
            int* nxt = &ctrl[8 + ((round + 1) & 1)];
            for (int base = 0; base < Ecur; base += NTHR) {
                int idx = base + tid;
                int e = 0; bool keep = false;
                unsigned long long sc = 0; int ru = 0, rv = 0;
                if (idx < Ecur) {
                    e = (round == 0) ? idx : (int)src[idx];
                    int u, v; edge_decode(e, u, v);
                    if (round == 0) { ru = peak[u]; rv = peak[v]; }  // par==identity on peaks
                    else            { ru = par[peak[u]]; rv = par[peak[v]]; }
                    if (ru != rv) {
                        keep = true;
                        unsigned long long hu = hk[u], hv = hk[v];
                        unsigned long long low = hu < hv ? hu : hv;
                        sc = (low << 13) | (unsigned)e;
                    }
                }
                unsigned m = __ballot_sync(FULLM, keep);
                int slot0 = 0;
                if ((tid & 31) == 0 && m) slot0 = atomicAdd(nxt, __popc(m));
                slot0 = __shfl_sync(FULLM, slot0, 0);
                if (keep) {
                    int rank = __popc(m & ((1u << (tid & 31)) - 1));
                    dst[slot0 + rank] = (unsigned short)e;
                    atomicMax(&best[ru], sc);
                    atomicMax(&best[rv], sc);
                }
            }
            __syncthreads();                                         // B2
            int Enext = ctrl[8 + ((round + 1) & 1)];
            if (Enext == 0) break;

            // record MST edges + stage hook targets (frozen par, frozen best).
            // dedup without bitmap: duplicate only when both roots share the SAME
            // best edge (best[tg]==sc) -> smaller-index root records.
            for (int t = tid; t < npk; t += NTHR) {
                int r = plist[t];
                if (par[r] == r) {
                    unsigned long long sc = best[r];
                    if (sc) {
                        int e = (int)(sc & 0x1FFF);
                        int u, v; edge_decode(e, u, v);
                        int ru = par[peak[u]], rv = par[peak[v]];
                        int tg = (ru == r) ? rv : ru;
                        tmp[r] = tg;
                        if (best[tg] != sc || r < tg) {
                            int slot = atomicAdd(&ctrl[0], 1);
                            mkey[slot] = ~sc;
                        }
                    }
                }
            }
            __syncthreads();                                         // B3

            // hook with fused mutual-2-cycle break (tmp/best frozen)
            for (int t = tid; t < npk; t += NTHR) {
                int r = plist[t];
                if (par[r] == r && best[r]) {
                    int tg = tmp[r];
                    bool mutual = (best[tg] != 0ull) && (tmp[tg] == r);
                    if (!(mutual && r < tg)) par[r] = tg;
                }
            }
            __syncthreads();                                         // B4

            // flatten peak entries, 1 barrier/iter
            for (int it = 0; it < 14; ++it) {
                int chg = 0;
                for (int t = tid; t < npk; t += NTHR) {
                    int p = plist[t];
                    int a = par[p]; int b = par[a];
                    if (a != b) { par[p] = b; chg = 1; }
                }
                if (!__syncthreads_or(chg)) break;
            }
            Ecur = Enext;
        }
        __syncthreads();
        const int nmst = min(ctrl[0], NPIX);

        // ---- pad + sort MST edges: ~score ascending == Kruskal order ----
        const int P = (nmst <= 1024) ? 1024 : ((nmst <= 2048) ? 2048 : 4096);
        for (int i = nmst + tid; i < P; i += NTHR) mkey[i] = ~0ull;
        __syncthreads();
        sort_keys(mkey, nmst, tid);

        // ---- pairing: parallel ready-edge rounds + chain over the remainder ----
        for (int t = tid; t < npk; t += NTHR) {
            int p = plist[t];
            par[p] = p;
            firstE[p] = SENT;
        }
        for (int i = tid; i < 128; i += NTHR) used[i] = 0u;
        __syncthreads();

        int remaining = nmst;
        for (int round = 0; round < 6 && remaining > 128; ++round) {
            const int tagbase = (15 - round) << 20;     // newer rounds have smaller tags
            // pass A: concurrent finds (path-halving safe: no unions running)
            for (int t = tid; t < nmst; t += NTHR) {
                if (used[t >> 5] & (1u << (t & 31))) continue;
                unsigned long long sc = ~mkey[t];
                int e = (int)(sc & 0x1FFF);
                int uu, vv; edge_decode(e, uu, vv);
                int ru = peak[uu];
                for (;;) { int p = par[ru]; if (p == ru) break; int gp = par[p]; par[ru] = gp; ru = gp; }
                int rv = peak[vv];
                for (;;) { int p = par[rv]; if (p == rv) break; int gp = par[p]; par[rv] = gp; rv = gp; }
                eA[t] = (unsigned short)ru;
                eB[t] = (unsigned short)rv;
                atomicMin(&firstE[ru], tagbase | t);
                atomicMin(&firstE[rv], tagbase | t);
            }
            __syncthreads();
            // pass B: commit ready edges (earliest remaining for BOTH components)
            int committed = 0;
            for (int t = tid; t < nmst; t += NTHR) {
                if (used[t >> 5] & (1u << (t & 31))) continue;
                int ru = eA[t], rv = eB[t];
                int tag = tagbase | t;
                if (firstE[ru] == tag && firstE[rv] == tag) {
                    unsigned long long sc = ~mkey[t];
                    int dIdx = 4095 - (int)((sc >> 13) & 0xFFF);
                    int young, elder;
                    if (hk[ru] > hk[rv]) { elder = ru; young = rv; }
                    else                 { elder = rv; young = ru; }
                    par[young] = elder;
                    float bv = val[young], dv = val[dIdx];
                    if (bv > dv) {
                        int slot = atomicAdd(&ctrl[3], 1);
                        barB[slot] = bv; barD[slot] = dv;
                    }
                    atomicOr(&used[t >> 5], 1u << (t & 31));
                    committed++;
                }
            }
            committed = __reduce_add_sync(FULLM, committed);
            if ((tid & 31) == 0 && committed) atomicAdd(&ctrl[11], committed);
            __syncthreads();
            remaining = nmst - ctrl[11];
        }
        __syncthreads();

        // compaction + ordered chain over the remainder (warp 0)
        if (tid < 32) {
            const int lane = tid;
            int cnt = 0;
            for (int base = 0; base < nmst; base += 32) {
                int t = base + lane;
                bool undone = (t < nmst) && !(used[t >> 5] & (1u << (t & 31)));
                unsigned m = __ballot_sync(FULLM, undone);
                if (undone) {
                    int rank = __popc(m & ((1u << lane) - 1));
                    eA[cnt + rank] = (unsigned short)t;
                }
                cnt += __popc(m);
            }
            for (int base = 0; base < cnt; base += 32) {
                int li = base + lane;
                bool has = li < cnt;
                unsigned long long sc = 0;
                if (has) sc = ~mkey[(int)eA[li]];
                kruskal_chunk(has, sc, par, peak, hk, val, barB, barD, &ctrl[3], lane);
            }
            // essential bar: single surviving root = global max pixel
            if (lane == 0 && maxv > minv) {
                int slot = atomicAdd(&ctrl[3], 1);
                barB[slot] = maxv; barD[slot] = minv;
            }
        }
        __syncthreads();
        const int nb = ctrl[3];

        // ---- sort bars by persistence descending ----
        const int P2 = (nb <= 1024) ? 1024 : ((nb <= 2048) ? 2048 : 4096);
        for (int i = tid; i < P2; i += NTHR) {
            if (i < nb) {
                float p = barB[i] - barD[i];
                mkey[i] = (((unsigned long long)(~ford(p))) << 32) | (unsigned)i;
            } else {
                mkey[i] = ~0ull;
            }
        }
        __syncthreads();
        sort_keys(mkey, nb, tid);

        for (int i = tid; i < nb; i += NTHR) {
            int idx = (int)(mkey[i] & 0xFFFFFFFFu);
            g_bb[s][i] = barB[idx];
            g_bd[s][i] = barD[idx];
        }
        if (tid == 0) g_k1[s] = nb;
    }

    // ---- fused loss: last block computes the final scalar ----
    __threadfence();
    __syncthreads();
    if (tid == 0) {
        int old = atomicAdd(&g_done, 1);
        ctrl[5] = (old == 7) ? 1 : 0;
    }
    __syncthreads();
    if (!ctrl[5]) return;
    __threadfence();

    float* red = (float*)best;
    float acc = 0.f;
    for (int ss = 0; ss < 4; ++ss) {
        const int K1 = g_k1[ss], K2 = g_k2[ss];
        const int m  = min(K1, K2);
        for (int t = tid; t < K1; t += NTHR) {
            float b = g_bb[ss][t], d = g_bd[ss][t];
            if (t < m) {
                float db = b - 1.0f;
                acc += db * db + d * d;
            } else {
                float q = b - d;
                acc += 0.5f * q * q;
            }
        }
        if (tid == 0 && K2 > K1)
            acc += 0.5f * (float)(K2 - K1);
    }
    #pragma unroll
    for (int off = 16; off > 0; off >>= 1)
        acc += __shfl_xor_sync(FULLM, acc, off);
    if ((tid & 31) == 0) red[tid >> 5] = acc;
    __syncthreads();
    if (tid < 32) {
        float a = red[tid];
        #pragma unroll
        for (int off = 16; off > 0; off >>= 1)
            a += __shfl_xor_sync(FULLM, a, off);
        if (tid == 0) {
            out[0] = a * 0.25f;
            g_done = 0;
        }
    }
}

extern "C" void kernel_launch(void* const* d_in, const int* in_sizes, int n_in,
                              void* d_out, int out_size)
{
    (void)in_sizes; (void)n_in; (void)out_size;
    const float* input  = (const float*)d_in[0];   // (4,2,64,64) float32
    const float* target = (const float*)d_in[1];   // (4,64,64)   float32

    cudaFuncSetAttribute(diagram_kernel,
                         cudaFuncAttributeMaxDynamicSharedMemorySize, SMEM_BYTES);
    diagram_kernel<<<8, NTHR, SMEM_BYTES>>>(input, target, (float*)d_out);
}

// round 16
// speedup vs baseline: 5.2321x; 1.0245x over previous
#include <cuda_runtime.h>
#include <math.h>
#include <stdint.h>

#define HW    64
#define NPIX  4096
#define NTHR  1024
#define REPS  (NPIX / NTHR)   // 4
#define FULLM 0xFFFFFFFFu
#define SENT  0x7FFFFFFF

__device__ int   g_k2[4];
__device__ int   g_k2f[4];      // zero-init; tgt sets 1, pred CAS-consumes back to 0
__device__ float g_partial[4];
__device__ int   g_done;        // zero-init; last pred block resets to 0

__device__ __forceinline__ unsigned ford(float f) {
    unsigned u = __float_as_uint(f);
    return (u & 0x80000000u) ? ~u : (u | 0x80000000u);
}
__device__ __forceinline__ float iford(unsigned m) {
    unsigned u = (m & 0x80000000u) ? (m ^ 0x80000000u) : ~m;
    return __uint_as_float(u);
}

// Shared layout: (same as R15)
//   val  f32[4096]   @0        16384
//   par  i32[4096]   @16384    16384
//   best u64[4096]   @32768    32768   (Boruvka best; then firstE int[]; then loss scratch)
//   mkey u64[4096]   @65536    32768
//   barB f32[4096]   @98304    16384   (alias: int tmp[4096])
//   barD f32[4096]   @114688   16384   (alias: u16 plist[4096])
//   used u32[256]    @131072    1024   (pairing done-bitmap)
//   ctrl i32[16]     @132096      64
//   hk   u64[4096]   @132160   32768
//   peak i32[4096]   @164928   16384
//   eA   u16[8192]   @181312   16384   (edge lists; then pairing root cache / chain list)
//   eB   u16[8192]   @197696   16384  -> 214080
#define SMEM_BYTES 214080

extern __shared__ unsigned char smem_raw[];

// division-free: e = (pixel << 1) | dir; dir 0 = right, 1 = down
__device__ __forceinline__ void edge_decode(int e, int& u, int& v) {
    u = e >> 1;
    v = u + ((e & 1) ? 64 : 1);
}

__device__ __forceinline__ void block_bitonic(unsigned long long* key, int P, int tid) {
    for (int k = 2; k <= P; k <<= 1) {
        for (int j = k >> 1; j > 0; j >>= 1) {
            for (int i = tid; i < P; i += NTHR) {
                int l = i ^ j;
                if (l > i) {
                    bool up = ((i & k) == 0);
                    unsigned long long a = key[i], b = key[l];
                    if ((a > b) == up) { key[i] = b; key[l] = a; }
                }
            }
            __syncthreads();
        }
    }
}

// hybrid bitonic for P == 1024 with 1024 threads (21 block barriers)
__device__ __forceinline__ void hybrid_bitonic_1024(unsigned long long* key, int tid) {
    const int lane = tid & 31;
    unsigned long long x = key[tid];
    #pragma unroll
    for (int k = 2; k <= 32; k <<= 1) {
        const bool dirUp = ((tid & k) == 0);
        #pragma unroll
        for (int j = k >> 1; j > 0; j >>= 1) {
            unsigned long long p = __shfl_xor_sync(FULLM, x, j);
            bool lower = ((lane & j) == 0);
            bool takeMin = (lower == dirUp);
            unsigned long long mn = (x < p) ? x : p;
            unsigned long long mx = (x < p) ? p : x;
            x = takeMin ? mn : mx;
        }
    }
    key[tid] = x;
    __syncthreads();
    #pragma unroll
    for (int k = 64; k <= 1024; k <<= 1) {
        const bool dirUp = ((tid & k) == 0);
        for (int j = k >> 1; j >= 32; j >>= 1) {
            int l = tid ^ j;
            if (l > tid) {
                unsigned long long a = key[tid], b = key[l];
                if ((a > b) == dirUp) { key[tid] = b; key[l] = a; }
            }
            __syncthreads();
        }
        x = key[tid];
        #pragma unroll
        for (int j = 16; j > 0; j >>= 1) {
            unsigned long long p = __shfl_xor_sync(FULLM, x, j);
            bool lower = ((lane & j) == 0);
            bool takeMin = (lower == dirUp);
            unsigned long long mn = (x < p) ? x : p;
            unsigned long long mx = (x < p) ? p : x;
            x = takeMin ? mn : mx;
        }
        key[tid] = x;
        __syncthreads();
    }
}

__device__ __forceinline__ void sort_keys(unsigned long long* key, int n, int tid) {
    if (n <= 1024) hybrid_bitonic_1024(key, tid);
    else           block_bitonic(key, (n <= 2048) ? 2048 : 4096, tid);
}

// one 32-edge speculative Kruskal chunk (proven R7 scheme)
__device__ __forceinline__ void kruskal_chunk(
    bool has, unsigned long long sc,
    int* par, const int* peak, const unsigned long long* hk,
    const float* val, float* barB, float* barD, int* nbars, int lane)
{
    int dIdx = 0, ru = 0, rv = 0;
    unsigned long long hu = 0, hv = 0;
    if (has) {
        int e = (int)(sc & 0x1FFF);
        int uu, vv; edge_decode(e, uu, vv);
        dIdx = 4095 - (int)((sc >> 13) & 0xFFF);
        ru = peak[uu];
        for (;;) { int p = par[ru]; if (p == ru) break; int gp = par[p]; par[ru] = gp; ru = gp; }
        rv = peak[vv];
        for (;;) { int p = par[rv]; if (p == rv) break; int gp = par[p]; par[rv] = gp; rv = gp; }
        hu = hk[ru]; hv = hk[rv];
    }
    __syncwarp(FULLM);
    int young = -1, elder = -1;
    #pragma unroll 4
    for (int k = 0; k < 32; ++k) {
        unsigned pk = 0xFFFFFFFFu;
        if (lane == k && has && ru != rv) {
            if (hu > hv) { elder = ru; young = rv; }
            else         { elder = rv; young = ru; }
            pk = ((unsigned)young << 16) | (unsigned)elder;
        }
        pk = __shfl_sync(FULLM, pk, k);
        if (pk != 0xFFFFFFFFu && lane > k) {
            int yk = (int)(pk >> 16), ek = (int)(pk & 0xFFFFu);
            if (ru == yk) { ru = ek; hu = hk[ek]; }
            if (rv == yk) { rv = ek; hv = hk[ek]; }
        }
    }
    if (young >= 0) {
        par[young] = elder;
        float bv = val[young];
        float dv = val[dIdx];
        if (bv > dv) {
            int slot = atomicAdd(nbars, 1);
            barB[slot] = bv; barD[slot] = dv;
        }
    }
    __syncwarp(FULLM);
}

__global__ void __launch_bounds__(NTHR)
diagram_kernel(const float* __restrict__ input, const float* __restrict__ target,
               float* __restrict__ out)
{
    const int s    = blockIdx.x & 3;
    const int kind = blockIdx.x >> 2;
    const int tid  = threadIdx.x;

    float* val = (float*)smem_raw;
    int*   par = (int*)(smem_raw + 16384);
    unsigned long long* best = (unsigned long long*)(smem_raw + 32768);
    int*   firstE = (int*)(smem_raw + 32768);
    float* red = (float*)(smem_raw + 32768);
    unsigned long long* mkey = (unsigned long long*)(smem_raw + 65536);
    float* barB = (float*)(smem_raw + 98304);
    int*   tmp  = (int*)  (smem_raw + 98304);
    float* barD = (float*)(smem_raw + 114688);
    unsigned short* plist = (unsigned short*)(smem_raw + 114688);
    unsigned* used = (unsigned*)(smem_raw + 131072);
    int* ctrl = (int*)(smem_raw + 132096);
    unsigned* uctrl = (unsigned*)ctrl;
    unsigned long long* hk = (unsigned long long*)(smem_raw + 132160);
    int* peak = (int*)(smem_raw + 164928);
    unsigned short* eA = (unsigned short*)(smem_raw + 181312);
    unsigned short* eB = (unsigned short*)(smem_raw + 197696);

    if (tid == 0) {
        ctrl[0] = 0; ctrl[3] = 0; uctrl[2] = FULLM; uctrl[6] = 0u;
        ctrl[7] = 0; ctrl[8] = 0; ctrl[9] = 0; ctrl[11] = 0;
    }
    __syncthreads();

    // ---- fill ----
    #pragma unroll
    for (int rep = 0; rep < REPS; ++rep) {
        int i = tid + rep * NTHR;
        float v;
        if (kind == 0) {
            float l0 = input[(s * 2 + 0) * NPIX + i];
            float l1 = input[(s * 2 + 1) * NPIX + i];
            v = 1.0f / (1.0f + expf(l0 - l1));   // == softmax fg channel
        } else {
            v = target[s * NPIX + i];
        }
        val[i] = v;
        if (kind == 0)
            hk[i] = (((unsigned long long)ford(v)) << 12) | (unsigned)(4095 - i);
        unsigned fb = ford(v);
        unsigned wmin = __reduce_min_sync(FULLM, fb);
        unsigned wmax = __reduce_max_sync(FULLM, fb);
        if ((tid & 31) == 0) { atomicMin(&uctrl[2], wmin); atomicMax(&uctrl[6], wmax); }
    }
    __syncthreads();
    const float minv = iford(uctrl[2]);
    const float maxv = iford(uctrl[6]);

    if (kind == 1) {
        // ======== binary target fast path: #components of {val > min} ========
        #pragma unroll
        for (int rep = 0; rep < REPS; ++rep) {
            int i = tid + rep * NTHR;
            par[i] = (val[i] > minv) ? i : SENT;
        }
        __syncthreads();
        for (int round = 0; round < 24; ++round) {
            int hooked = 0;
            #pragma unroll
            for (int rep = 0; rep < REPS; ++rep) {
                int i = tid + rep * NTHR;
                int ri = par[i];
                if (ri != SENT) {
                    int r = i >> 6, c = i & 63;
                    int m = ri;
                    if (r > 0)  { int q = par[i - 64]; if (q < m) m = q; }
                    if (r < 63) { int q = par[i + 64]; if (q < m) m = q; }
                    if (c > 0)  { int q = par[i - 1];  if (q < m) m = q; }
                    if (c < 63) { int q = par[i + 1];  if (q < m) m = q; }
                    if (m < ri) { atomicMin(&par[ri], m); hooked = 1; }
                }
            }
            if (!__syncthreads_or(hooked)) break;
            for (int it = 0; it < 13; ++it) {
                int chg = 0;
                #pragma unroll
                for (int rep = 0; rep < REPS; ++rep) {
                    int i = tid + rep * NTHR;
                    int p = par[i];
                    if (p != SENT) {
                        int pp = par[p];
                        if (p != pp) { par[i] = pp; chg = 1; }
                    }
                }
                if (!__syncthreads_or(chg)) break;
            }
        }
        int cnt = 0;
        #pragma unroll
        for (int rep = 0; rep < REPS; ++rep) {
            int i = tid + rep * NTHR;
            if (par[i] == i) cnt++;
        }
        cnt = __reduce_add_sync(FULLM, cnt);
        if ((tid & 31) == 0) atomicAdd(&ctrl[3], cnt);
        __syncthreads();
        if (tid == 0) {
            g_k2[s] = ctrl[3];
            __threadfence();
            atomicExch(&g_k2f[s], 1);        // publish K2 to the pred block
        }
        return;
    }

    // ======== pred path ========
    // steepest strictly-higher neighbor hook -> peak labels
    #pragma unroll
    for (int rep = 0; rep < REPS; ++rep) {
        int i = tid + rep * NTHR;
        unsigned long long h = hk[i];
        int r = i >> 6, c = i & 63;
        int p = i;
        if      (r < 63 && hk[i + 64] > h) p = i + 64;
        else if (r > 0  && hk[i - 64] > h) p = i - 64;
        else if (c < 63 && hk[i + 1]  > h) p = i + 1;
        else if (c > 0  && hk[i - 1]  > h) p = i - 1;
        par[i] = p;
    }
    __syncthreads();
    for (int it = 0; it < 12; ++it) {
        int chg = 0;
        #pragma unroll
        for (int rep = 0; rep < REPS; ++rep) {
            int i = tid + rep * NTHR;
            int p = par[i]; int pp = par[p];
            if (p != pp) { par[i] = pp; chg = 1; }
        }
        if (!__syncthreads_or(chg)) break;
    }
    #pragma unroll
    for (int rep = 0; rep < REPS; ++rep) {
        int i = tid + rep * NTHR;
        int p = par[i];
        peak[i] = p;
        if (p == i) { int slot = atomicAdd(&ctrl[7], 1); plist[slot] = (unsigned short)i; }
    }
    __syncthreads();
    const int npk = ctrl[7];

    // ---- Boruvka over regions with compacted edge lists ----
    int Ecur = 2 * NPIX;   // round 0: (pixel, dir) enumeration domain
    for (int round = 0; Ecur > 0 && round < 20; ++round) {
        if (tid == 0) ctrl[8 + ((round + 1) & 1)] = 0;
        for (int t = tid; t < npk; t += NTHR) best[plist[t]] = 0ull;
        __syncthreads();                                         // B1

        const unsigned short* src = (round & 1) ? eB : eA;
        unsigned short*       dst = (round & 1) ? eA : eB;
        int* nxt = &ctrl[8 + ((round + 1) & 1)];
        for (int base = 0; base < Ecur; base += NTHR) {
            int idx = base + tid;
            int e = 0; bool keep = false;
            unsigned long long sc = 0; int ru = 0, rv = 0;
            if (idx < Ecur) {
                bool valid = true;
                if (round == 0) {
                    e = idx;
                    int u0 = e >> 1;
                    valid = (e & 1) ? (u0 < 4032) : ((u0 & 63) != 63);
                } else {
                    e = (int)src[idx];
                }
                if (valid) {
                    int u, v; edge_decode(e, u, v);
                    if (round == 0) { ru = peak[u]; rv = peak[v]; }  // par==identity on peaks
                    else            { ru = par[peak[u]]; rv = par[peak[v]]; }
                    if (ru != rv) {
                        keep = true;
                        unsigned long long hu = hk[u], hv = hk[v];
                        unsigned long long low = hu < hv ? hu : hv;
                        sc = (low << 13) | (unsigned)e;
                    }
                }
            }
            unsigned m = __ballot_sync(FULLM, keep);
            int slot0 = 0;
            if ((tid & 31) == 0 && m) slot0 = atomicAdd(nxt, __popc(m));
            slot0 = __shfl_sync(FULLM, slot0, 0);
            if (keep) {
                int rank = __popc(m & ((1u << (tid & 31)) - 1));
                dst[slot0 + rank] = (unsigned short)e;
                atomicMax(&best[ru], sc);
                atomicMax(&best[rv], sc);
            }
        }
        __syncthreads();                                         // B2
        int Enext = ctrl[8 + ((round + 1) & 1)];
        if (Enext == 0) break;

        // record MST edges + stage hook targets (frozen par, frozen best).
        // dedup without bitmap: duplicate only when both roots share the SAME
        // best edge (best[tg]==sc) -> smaller-index root records.
        for (int t = tid; t < npk; t += NTHR) {
            int r = plist[t];
            if (par[r] == r) {
                unsigned long long sc = best[r];
                if (sc) {
                    int e = (int)(sc & 0x1FFF);
                    int u, v; edge_decode(e, u, v);
                    int ru = par[peak[u]], rv = par[peak[v]];
                    int tg = (ru == r) ? rv : ru;
                    tmp[r] = tg;
                    if (best[tg] != sc || r < tg) {
                        int slot = atomicAdd(&ctrl[0], 1);
                        mkey[slot] = ~sc;
                    }
                }
            }
        }
        __syncthreads();                                         // B3

        // hook with fused mutual-2-cycle break (tmp/best frozen)
        for (int t = tid; t < npk; t += NTHR) {
            int r = plist[t];
            if (par[r] == r && best[r]) {
                int tg = tmp[r];
                bool mutual = (best[tg] != 0ull) && (tmp[tg] == r);
                if (!(mutual && r < tg)) par[r] = tg;
            }
        }
        __syncthreads();                                         // B4

        // flatten peak entries, 1 barrier/iter
        for (int it = 0; it < 14; ++it) {
            int chg = 0;
            for (int t = tid; t < npk; t += NTHR) {
                int p = plist[t];
                int a = par[p]; int b = par[a];
                if (a != b) { par[p] = b; chg = 1; }
            }
            if (!__syncthreads_or(chg)) break;
        }
        Ecur = Enext;
    }
    __syncthreads();
    const int nmst = min(ctrl[0], NPIX);

    // ---- pad + sort MST edges: ~score ascending == Kruskal order ----
    const int P = (nmst <= 1024) ? 1024 : ((nmst <= 2048) ? 2048 : 4096);
    for (int i = nmst + tid; i < P; i += NTHR) mkey[i] = ~0ull;
    __syncthreads();
    sort_keys(mkey, nmst, tid);

    // ---- pairing: parallel ready-edge rounds + chain over the remainder ----
    for (int t = tid; t < npk; t += NTHR) {
        int p = plist[t];
        par[p] = p;
        firstE[p] = SENT;
    }
    for (int i = tid; i < 128; i += NTHR) used[i] = 0u;
    __syncthreads();

    int remaining = nmst;
    for (int round = 0; round < 6 && remaining > 128; ++round) {
        const int tagbase = (15 - round) << 20;     // newer rounds have smaller tags
        // pass A: concurrent finds (path-halving safe: no unions running)
        for (int t = tid; t < nmst; t += NTHR) {
            if (used[t >> 5] & (1u << (t & 31))) continue;
            unsigned long long sc = ~mkey[t];
            int e = (int)(sc & 0x1FFF);
            int uu, vv; edge_decode(e, uu, vv);
            int ru = peak[uu];
            for (;;) { int p = par[ru]; if (p == ru) break; int gp = par[p]; par[ru] = gp; ru = gp; }
            int rv = peak[vv];
            for (;;) { int p = par[rv]; if (p == rv) break; int gp = par[p]; par[rv] = gp; rv = gp; }
            eA[t] = (unsigned short)ru;
            eB[t] = (unsigned short)rv;
            atomicMin(&firstE[ru], tagbase | t);
            atomicMin(&firstE[rv], tagbase | t);
        }
        __syncthreads();
        // pass B: commit ready edges (earliest remaining for BOTH components)
        int committed = 0;
        for (int t = tid; t < nmst; t += NTHR) {
            if (used[t >> 5] & (1u << (t & 31))) continue;
            int ru = eA[t], rv = eB[t];
            int tag = tagbase | t;
            if (firstE[ru] == tag && firstE[rv] == tag) {
                unsigned long long sc = ~mkey[t];
                int dIdx = 4095 - (int)((sc >> 13) & 0xFFF);
                int young, elder;
                if (hk[ru] > hk[rv]) { elder = ru; young = rv; }
                else                 { elder = rv; young = ru; }
                par[young] = elder;
                float bv = val[young], dv = val[dIdx];
                if (bv > dv) {
                    int slot = atomicAdd(&ctrl[3], 1);
                    barB[slot] = bv; barD[slot] = dv;
                }
                atomicOr(&used[t >> 5], 1u << (t & 31));
                committed++;
            }
        }
        committed = __reduce_add_sync(FULLM, committed);
        if ((tid & 31) == 0 && committed) atomicAdd(&ctrl[11], committed);
        __syncthreads();
        remaining = nmst - ctrl[11];
    }
    __syncthreads();

    // compaction + ordered chain over the remainder (warp 0)
    if (tid < 32) {
        const int lane = tid;
        int cnt = 0;
        for (int base = 0; base < nmst; base += 32) {
            int t = base + lane;
            bool undone = (t < nmst) && !(used[t >> 5] & (1u << (t & 31)));
            unsigned m = __ballot_sync(FULLM, undone);
            if (undone) {
                int rank = __popc(m & ((1u << lane) - 1));
                eA[cnt + rank] = (unsigned short)t;
            }
            cnt += __popc(m);
        }
        for (int base = 0; base < cnt; base += 32) {
            int li = base + lane;
            bool has = li < cnt;
            unsigned long long sc = 0;
            if (has) sc = ~mkey[(int)eA[li]];
            kruskal_chunk(has, sc, par, peak, hk, val, barB, barD, &ctrl[3], lane);
        }
        // essential bar: single surviving root = global max pixel
        if (lane == 0 && maxv > minv) {
            int slot = atomicAdd(&ctrl[3], 1);
            barB[slot] = maxv; barD[slot] = minv;
        }
    }
    __syncthreads();
    const int nb = ctrl[3];       // K1

    // ---- consume K2 from the target block (handshake) ----
    if (tid == 0) {
        while (atomicCAS(&g_k2f[s], 1, 0) == 0) { }
        __threadfence();
        ctrl[12] = g_k2[s];
    }
    __syncthreads();
    const int K2 = ctrl[12];

    // ---- sort bars by persistence descending ----
    const int P2 = (nb <= 1024) ? 1024 : ((nb <= 2048) ? 2048 : 4096);
    for (int i = tid; i < P2; i += NTHR) {
        if (i < nb) {
            float p = barB[i] - barD[i];
            mkey[i] = (((unsigned long long)(~ford(p))) << 32) | (unsigned)i;
        } else {
            mkey[i] = ~0ull;
        }
    }
    __syncthreads();
    sort_keys(mkey, nb, tid);

    // ---- per-sample loss, computed locally from smem bars ----
    const int m = min(nb, K2);
    float acc = 0.f;
    for (int i = tid; i < nb; i += NTHR) {
        int idx = (int)(mkey[i] & 0xFFFFFFFFu);
        float b = barB[idx], d = barD[idx];
        if (i < m) {
            float db = b - 1.0f;
            acc += db * db + d * d;
        } else {
            float q = b - d;
            acc += 0.5f * q * q;
        }
    }
    if (tid == 0 && K2 > nb) acc += 0.5f * (float)(K2 - nb);
    #pragma unroll
    for (int off = 16; off > 0; off >>= 1)
        acc += __shfl_xor_sync(FULLM, acc, off);
    if ((tid & 31) == 0) red[tid >> 5] = acc;
    __syncthreads();
    if (tid < 32) {
        float a = red[tid];
        #pragma unroll
        for (int off = 16; off > 0; off >>= 1)
            a += __shfl_xor_sync(FULLM, a, off);
        if (tid == 0) {
            g_partial[s] = a;
            __threadfence();
            int old = atomicAdd(&g_done, 1);
            if (old == 3) {                      // last pred block finalizes
                __threadfence();
                out[0] = (g_partial[0] + g_partial[1] +
                          g_partial[2] + g_partial[3]) * 0.25f;
                g_done = 0;
            }
        }
    }
}

extern "C" void kernel_launch(void* const* d_in, const int* in_sizes, int n_in,
                              void* d_out, int out_size)
{
    (void)in_sizes; (void)n_in; (void)out_size;
    const float* input  = (const float*)d_in[0];   // (4,2,64,64) float32
    const float* target = (const float*)d_in[1];   // (4,64,64)   float32

    cudaFuncSetAttribute(diagram_kernel,
                         cudaFuncAttributeMaxDynamicSharedMemorySize, SMEM_BYTES);
    diagram_kernel<<<8, NTHR, SMEM_BYTES>>>(input, target, (float*)d_out);
}